// round 8
// baseline (speedup 1.0000x reference)
#include <cuda_runtime.h>

// Decoder: T_IN=12, B=65536, H=64, T_OUT=12, OVERLAP=3
// Phase-split design, 128 threads / 16 batches per CTA, target 3 CTAs/SM:
//   Phase A (attention+out): 8-lane group owns one batch, lane owns 8 dims,
//                            all math as packed fma.rn.f32x2.
//   Phase B (GRU matvec+gates): 2x2 (row-half x batch-group) warp split.
// Per-lane GRU/linear params live in SMEM (not registers) to cut reg count.
// NOTE: all 16-byte-unit row strides are 16 units per 64-float batch row.

#define FULLMASK 0xFFFFFFFFu

constexpr int T_IN  = 12;
constexpr int T_OUT = 12;
constexpr int Bz    = 65536;
constexpr int H     = 64;
constexpr int WARPS = 4;
constexpr int THREADS = WARPS * 32;
constexpr int BPC   = 16;            // batches per CTA
constexpr int K4    = 16;            // 16 float4 chunks over k=64

constexpr int W4_ELEMS = K4 * 192;   // 3072 float4 = 48KB
// smem floats: W(12288) hA(1024) hG(1024) L(64) gp(768) bh(192) wl(64)
constexpr int OFF_HA = W4_ELEMS * 4;
constexpr int OFF_HG = OFF_HA + BPC * H;
constexpr int OFF_L  = OFF_HG + BPC * H;
constexpr int OFF_GP = OFF_L + BPC * 4;
constexpr int OFF_BH = OFF_GP + 192 * 4;
constexpr int OFF_WL = OFF_BH + 192;
constexpr int SMEM_FLOATS = OFF_WL + 64;
constexpr int SMEM_BYTES = SMEM_FLOATS * 4;   // 61,696 B -> 3 CTAs/SM fits

typedef unsigned long long u64;

__device__ __forceinline__ void ffma2(u64& d, u64 a, u64 b) {
    asm("fma.rn.f32x2 %0, %1, %2, %0;" : "+l"(d) : "l"(a), "l"(b));
}
__device__ __forceinline__ u64 packf2(float lo, float hi) {
    u64 r;
    asm("mov.b64 %0, {%1, %2};" : "=l"(r) : "f"(lo), "f"(hi));
    return r;
}
__device__ __forceinline__ float f2lo(u64 v) {
    return __uint_as_float((unsigned)(v & 0xFFFFFFFFull));
}
__device__ __forceinline__ float f2hi(u64 v) {
    return __uint_as_float((unsigned)(v >> 32));
}
__device__ __forceinline__ float sigf(float x) {
    return __fdividef(1.0f, 1.0f + __expf(-x));
}
__device__ __forceinline__ float tanhfast(float x) {
    return __fdividef(2.0f, 1.0f + __expf(-2.0f * x)) - 1.0f;
}
// sum over 8 dims held as 4 f32x2 pairs: sum_i a[i] .* b[i]
__device__ __forceinline__ float dotp(const u64* a, const u64* b) {
    u64 d = 0ull;
    ffma2(d, a[0], b[0]); ffma2(d, a[1], b[1]);
    ffma2(d, a[2], b[2]); ffma2(d, a[3], b[3]);
    return f2lo(d) + f2hi(d);
}

__global__ void __launch_bounds__(THREADS, 3)
decoder_kernel(const float* __restrict__ enc,    // (12, B, 64)
               const float* __restrict__ hid0,   // (B, 64)
               const float* __restrict__ last,   // (B, 3)
               const float* __restrict__ Wih,    // (192, 3)
               const float* __restrict__ Whh,    // (192, 64)
               const float* __restrict__ bih,    // (192)
               const float* __restrict__ bhh,    // (192)
               const float* __restrict__ Wlin,   // (1, 64)
               const float* __restrict__ blin,   // (1)
               float* __restrict__ out)          // (B, 12)
{
    extern __shared__ float smem[];
    float4* W4sh = reinterpret_cast<float4*>(smem);
    float*  hAsh = smem + OFF_HA;
    float*  hGsh = smem + OFF_HG;
    float4* Lsh  = reinterpret_cast<float4*>(smem + OFF_L);
    float4* gpsh = reinterpret_cast<float4*>(smem + OFF_GP);   // {wih0,1,2,bih}
    float*  bhsh = smem + OFF_BH;
    float*  wlsh = smem + OFF_WL;

    const int tid  = threadIdx.x;
    const int lane = tid & 31;
    const int w    = tid >> 5;
    const int cb0  = blockIdx.x * BPC;

    // ---- stage W_hh as float4 k-chunks: W4sh[k4*192 + j] = Whh[j][4k4..+3]
    const float4* Whh4 = reinterpret_cast<const float4*>(Whh);
    for (int i = tid; i < W4_ELEMS; i += THREADS) {
        int k4 = i / 192, j = i - k4 * 192;
        W4sh[i] = __ldg(&Whh4[j * 16 + k4]);
    }
    // ---- stage params
    for (int j = tid; j < 192; j += THREADS) {
        gpsh[j] = make_float4(__ldg(&Wih[j * 3 + 0]), __ldg(&Wih[j * 3 + 1]),
                              __ldg(&Wih[j * 3 + 2]), __ldg(&bih[j]));
        bhsh[j] = __ldg(&bhh[j]);
    }
    if (tid < 64) wlsh[tid] = __ldg(&Wlin[tid]);
    // ---- stage hG = hid0, Lsh = last
    const float4* hid04 = reinterpret_cast<const float4*>(hid0);
    float4* hG4 = reinterpret_cast<float4*>(hGsh);
    for (int i = tid; i < BPC * 16; i += THREADS)
        hG4[i] = __ldg(&hid04[cb0 * 16 + i]);
    if (tid < BPC) {
        int gb = cb0 + tid;
        Lsh[tid] = make_float4(__ldg(&last[gb * 3 + 0]),
                               __ldg(&last[gb * 3 + 1]),
                               __ldg(&last[gb * 3 + 2]), 0.0f);
    }

    // ---- Phase A identity: 8-lane group -> one batch, lane -> 8 dims
    const int sub = lane >> 3, lg = lane & 7;
    const int bA  = w * 4 + sub;
    const int gbA = cb0 + bA;
    const float bl = __ldg(blin);

    // encoder slice in registers as packed f32x2 pairs: 4 u64-pairs x 12 t
    // ulonglong2 = 16B = 4 floats; one (t,b) row = 64 floats = 16 units.
    const ulonglong2* enc2 = reinterpret_cast<const ulonglong2*>(enc);
    u64 ev[T_IN][4];
#pragma unroll
    for (int t = 0; t < T_IN; t++) {
        int idx = (t * Bz + gbA) * 16 + lg * 2;
        ulonglong2 a = __ldg(&enc2[idx]);
        ulonglong2 b = __ldg(&enc2[idx + 1]);
        ev[t][0] = a.x; ev[t][1] = a.y; ev[t][2] = b.x; ev[t][3] = b.y;
    }

    // ---- Phase B identity: row-half q, batch-group of 8
    const int q   = (w >> 1) * 32;
    const int bb0 = (w & 1) * 8;

    __syncthreads();

    const ulonglong2* W2   = reinterpret_cast<const ulonglong2*>(W4sh);
    const ulonglong2* HA2  = reinterpret_cast<const ulonglong2*>(hAsh);
    const ulonglong2* HG2  = reinterpret_cast<const ulonglong2*>(hGsh);
    const ulonglong2* WL2  = reinterpret_cast<const ulonglong2*>(wlsh);
    ulonglong2* HA2w = reinterpret_cast<ulonglong2*>(hAsh);

#pragma unroll 1
    for (int step = 0; step < T_OUT; step++) {
        // ================= Phase A: out(step-1) + attention =================
        u64 hp[4];
        {
            ulonglong2 a = HG2[bA * 16 + lg * 2];       // 16 units per batch row
            ulonglong2 b = HG2[bA * 16 + lg * 2 + 1];
            hp[0] = a.x; hp[1] = a.y; hp[2] = b.x; hp[3] = b.y;
        }

        if (step > 0) {
            u64 wlp[4];
            ulonglong2 a = WL2[lg * 2], b = WL2[lg * 2 + 1];
            wlp[0] = a.x; wlp[1] = a.y; wlp[2] = b.x; wlp[3] = b.y;
            float o = dotp(hp, wlp);
            o += __shfl_xor_sync(FULLMASK, o, 4);
            o += __shfl_xor_sync(FULLMASK, o, 2);
            o += __shfl_xor_sync(FULLMASK, o, 1);
            o += bl;
            if (lg == 0) {
                float4 L = Lsh[bA];
                out[gbA * T_OUT + step - 1] = o;
                Lsh[bA] = make_float4(o, L.x, L.y, 0.0f);
            }
        }

        float p[T_IN];
#pragma unroll
        for (int t = 0; t < T_IN; t++)
            p[t] = dotp(ev[t], hp);
#pragma unroll
        for (int off = 4; off > 0; off >>= 1)
#pragma unroll
            for (int t = 0; t < T_IN; t++)
                p[t] += __shfl_xor_sync(FULLMASK, p[t], off);

        float m = p[0];
#pragma unroll
        for (int t = 1; t < T_IN; t++) m = fmaxf(m, p[t]);
        float s = 0.0f;
#pragma unroll
        for (int t = 0; t < T_IN; t++) { p[t] = __expf(p[t] - m); s += p[t]; }
        float inv = __fdividef(1.0f, s);

        u64 cp[4] = {0ull, 0ull, 0ull, 0ull};
#pragma unroll
        for (int t = 0; t < T_IN; t++) {
            u64 pp = packf2(p[t], p[t]);
            ffma2(cp[0], ev[t][0], pp); ffma2(cp[1], ev[t][1], pp);
            ffma2(cp[2], ev[t][2], pp); ffma2(cp[3], ev[t][3], pp);
        }
        u64 ip = packf2(inv, inv);
        ffma2(hp[0], cp[0], ip); ffma2(hp[1], cp[1], ip);
        ffma2(hp[2], cp[2], ip); ffma2(hp[3], cp[3], ip);

        HA2w[bA * 16 + lg * 2]     = make_ulonglong2(hp[0], hp[1]);
        HA2w[bA * 16 + lg * 2 + 1] = make_ulonglong2(hp[2], hp[3]);
        __syncthreads();

        // ============ Phase B: gh = hA @ W_hh^T (rows q..), gates ============
        u64 acc[3][8];
#pragma unroll
        for (int g = 0; g < 3; g++)
#pragma unroll
            for (int b = 0; b < 8; b++) acc[g][b] = 0ull;

#pragma unroll 1
        for (int k4 = 0; k4 < K4; k4++) {
            ulonglong2 wv0 = W2[k4 * 192 + q + lane];
            ulonglong2 wv1 = W2[k4 * 192 + 64 + q + lane];
            ulonglong2 wv2 = W2[k4 * 192 + 128 + q + lane];
#pragma unroll
            for (int half = 0; half < 2; half++) {
                ulonglong2 hv[4];
#pragma unroll
                for (int b4 = 0; b4 < 4; b4++)
                    hv[b4] = HA2[(bb0 + half * 4 + b4) * 16 + k4];
#pragma unroll
                for (int b4 = 0; b4 < 4; b4++) {
                    int b = half * 4 + b4;
                    ffma2(acc[0][b], wv0.x, hv[b4].x); ffma2(acc[0][b], wv0.y, hv[b4].y);
                    ffma2(acc[1][b], wv1.x, hv[b4].x); ffma2(acc[1][b], wv1.y, hv[b4].y);
                    ffma2(acc[2][b], wv2.x, hv[b4].x); ffma2(acc[2][b], wv2.y, hv[b4].y);
                }
            }
        }

        // per-lane row params from smem
        float4 gp0 = gpsh[q + lane];
        float4 gp1 = gpsh[64 + q + lane];
        float4 gp2 = gpsh[128 + q + lane];
        float bh0 = bhsh[q + lane];
        float bh1 = bhsh[64 + q + lane];
        float bh2 = bhsh[128 + q + lane];

#pragma unroll
        for (int b = 0; b < 8; b++) {
            float ghr = f2lo(acc[0][b]) + f2hi(acc[0][b]) + bh0;
            float ghz = f2lo(acc[1][b]) + f2hi(acc[1][b]) + bh1;
            float ghn = f2lo(acc[2][b]) + f2hi(acc[2][b]) + bh2;
            float4 L = Lsh[bb0 + b];
            float gir = fmaf(gp0.x, L.x, fmaf(gp0.y, L.y, fmaf(gp0.z, L.z, gp0.w)));
            float giz = fmaf(gp1.x, L.x, fmaf(gp1.y, L.y, fmaf(gp1.z, L.z, gp1.w)));
            float gin = fmaf(gp2.x, L.x, fmaf(gp2.y, L.y, fmaf(gp2.z, L.z, gp2.w)));
            float r = sigf(gir + ghr);
            float z = sigf(giz + ghz);
            float n = tanhfast(fmaf(r, ghn, gin));
            float hprev = hAsh[(bb0 + b) * H + q + lane];
            hGsh[(bb0 + b) * H + q + lane] = fmaf(z, hprev - n, n);
        }
        __syncthreads();
    }

    // ---- final output (step T_OUT-1) from hG ----
    {
        u64 hp[4], wlp[4];
        ulonglong2 a = HG2[bA * 16 + lg * 2];
        ulonglong2 b = HG2[bA * 16 + lg * 2 + 1];
        hp[0] = a.x; hp[1] = a.y; hp[2] = b.x; hp[3] = b.y;
        ulonglong2 c = WL2[lg * 2], d = WL2[lg * 2 + 1];
        wlp[0] = c.x; wlp[1] = c.y; wlp[2] = d.x; wlp[3] = d.y;
        float o = dotp(hp, wlp);
        o += __shfl_xor_sync(FULLMASK, o, 4);
        o += __shfl_xor_sync(FULLMASK, o, 2);
        o += __shfl_xor_sync(FULLMASK, o, 1);
        o += bl;
        if (lg == 0) out[gbA * T_OUT + T_OUT - 1] = o;
    }
}

extern "C" void kernel_launch(void* const* d_in, const int* in_sizes, int n_in,
                              void* d_out, int out_size) {
    const float* enc  = (const float*)d_in[0];
    const float* hid0 = (const float*)d_in[1];
    const float* last = (const float*)d_in[2];
    const float* Wih  = (const float*)d_in[3];
    const float* Whh  = (const float*)d_in[4];
    const float* bih  = (const float*)d_in[5];
    const float* bhh  = (const float*)d_in[6];
    const float* Wlin = (const float*)d_in[7];
    const float* blin = (const float*)d_in[8];
    float* out = (float*)d_out;

    cudaFuncSetAttribute(decoder_kernel,
                         cudaFuncAttributeMaxDynamicSharedMemorySize,
                         SMEM_BYTES);

    dim3 grid(Bz / BPC);   // 4096 CTAs
    decoder_kernel<<<grid, THREADS, SMEM_BYTES>>>(
        enc, hid0, last, Wih, Whh, bih, bhh, Wlin, blin, out);
}

// round 9
// speedup vs baseline: 1.9341x; 1.9341x over previous
#include <cuda_runtime.h>

// Decoder: T_IN=12, B=65536, H=64, T_OUT=12, OVERLAP=3
// 128 threads / 16 batches per CTA.
//   Phase A (attention+out): 8-lane group owns one batch, lane owns 8 dims,
//                            plain float4 fp32 math (R5 form).
//   Phase B (GRU matvec): tf32 mma.sync.m16n8k8 — M=16 batches, each warp
//                         computes 48 rows (dims w*16..+15 for gates r,z,n).
//   W_hh staged once into SMEM pre-swizzled in B-fragment layout (tf32).
//   hA/hG stored with 68-float row pitch for conflict-free fragment loads.

#define FULLMASK 0xFFFFFFFFu

constexpr int T_IN  = 12;
constexpr int T_OUT = 12;
constexpr int Bz    = 65536;
constexpr int WARPS = 4;
constexpr int THREADS = WARPS * 32;
constexpr int BPC   = 16;            // batches per CTA
constexpr int HPAD  = 68;            // padded row pitch (floats) for hA/hG

// SMEM float offsets
constexpr int WFRAG_N   = 4 * 6 * 8 * 32;      // warps x ntile x ktile x lane (uint2)
constexpr int OFF_HA    = WFRAG_N * 2;          // 12288
constexpr int OFF_HG    = OFF_HA + BPC * HPAD;  // +1088
constexpr int OFF_L     = OFF_HG + BPC * HPAD;  // +1088
constexpr int OFF_GP    = OFF_L + BPC * 4;      // +64
constexpr int OFF_BH    = OFF_GP + 192 * 4;     // +768
constexpr int OFF_WL    = OFF_BH + 192;         // +192
constexpr int SMEM_FLOATS = OFF_WL + 64;
constexpr int SMEM_BYTES  = SMEM_FLOATS * 4;    // 62,208 B

__device__ __forceinline__ unsigned cvt_tf32(float x) {
    unsigned r;
    asm("cvt.rna.tf32.f32 %0, %1;" : "=r"(r) : "f"(x));
    return r;
}
__device__ __forceinline__ void mma_tf32(float& d0, float& d1, float& d2, float& d3,
                                         unsigned a0, unsigned a1, unsigned a2, unsigned a3,
                                         unsigned b0, unsigned b1) {
    asm("mma.sync.aligned.m16n8k8.row.col.f32.tf32.tf32.f32 "
        "{%0,%1,%2,%3}, {%4,%5,%6,%7}, {%8,%9}, {%0,%1,%2,%3};"
        : "+f"(d0), "+f"(d1), "+f"(d2), "+f"(d3)
        : "r"(a0), "r"(a1), "r"(a2), "r"(a3), "r"(b0), "r"(b1));
}
__device__ __forceinline__ float sigf(float x) {
    return __fdividef(1.0f, 1.0f + __expf(-x));
}
__device__ __forceinline__ float tanhfast(float x) {
    return __fdividef(2.0f, 1.0f + __expf(-2.0f * x)) - 1.0f;
}
__device__ __forceinline__ float dot8(float4 a, float4 b, float4 c, float4 d) {
    float s = a.x * b.x;
    s = fmaf(a.y, b.y, s); s = fmaf(a.z, b.z, s); s = fmaf(a.w, b.w, s);
    s = fmaf(c.x, d.x, s); s = fmaf(c.y, d.y, s);
    s = fmaf(c.z, d.z, s); s = fmaf(c.w, d.w, s);
    return s;
}

__global__ void __launch_bounds__(THREADS, 2)
decoder_kernel(const float* __restrict__ enc,    // (12, B, 64)
               const float* __restrict__ hid0,   // (B, 64)
               const float* __restrict__ last,   // (B, 3)
               const float* __restrict__ Wih,    // (192, 3)
               const float* __restrict__ Whh,    // (192, 64)
               const float* __restrict__ bih,    // (192)
               const float* __restrict__ bhh,    // (192)
               const float* __restrict__ Wlin,   // (1, 64)
               const float* __restrict__ blin,   // (1)
               float* __restrict__ out)          // (B, 12)
{
    extern __shared__ float smem[];
    uint2*  Wfr  = reinterpret_cast<uint2*>(smem);
    float*  hAsh = smem + OFF_HA;
    float*  hGsh = smem + OFF_HG;
    float4* Lsh  = reinterpret_cast<float4*>(smem + OFF_L);
    float4* gpsh = reinterpret_cast<float4*>(smem + OFF_GP);   // {wih0,1,2,bih}
    float*  bhsh = smem + OFF_BH;
    float*  wlsh = smem + OFF_WL;

    const int tid  = threadIdx.x;
    const int lane = tid & 31;
    const int w    = tid >> 5;
    const int cb0  = blockIdx.x * BPC;

    // ---- stage W_hh into B-fragment layout (tf32), once ----
    // Wfr[((ww*6+nt)*8+kt)*32 + ln] = {W[j][kt*8+t4], W[j][kt*8+t4+4]} (tf32)
    // where j = (nt>>1)*64 + ww*16 + (nt&1)*8 + (ln>>2), t4 = ln&3
    for (int i = tid; i < WFRAG_N; i += THREADS) {
        int ww  = i / 1536;
        int rem = i - ww * 1536;
        int nt  = rem >> 8;
        int rm2 = rem & 255;
        int kt  = rm2 >> 5;
        int ln  = rm2 & 31;
        int gg  = ln >> 2, t4 = ln & 3;
        int j   = ((nt >> 1) << 6) + ww * 16 + ((nt & 1) << 3) + gg;
        float b0 = __ldg(&Whh[j * 64 + kt * 8 + t4]);
        float b1 = __ldg(&Whh[j * 64 + kt * 8 + t4 + 4]);
        Wfr[i] = make_uint2(cvt_tf32(b0), cvt_tf32(b1));
    }
    // ---- stage params ----
    for (int j = tid; j < 192; j += THREADS) {
        gpsh[j] = make_float4(__ldg(&Wih[j * 3 + 0]), __ldg(&Wih[j * 3 + 1]),
                              __ldg(&Wih[j * 3 + 2]), __ldg(&bih[j]));
        bhsh[j] = __ldg(&bhh[j]);
    }
    if (tid < 64) wlsh[tid] = __ldg(&Wlin[tid]);
    // ---- stage hG = hid0 (padded rows), Lsh = last ----
    {
        const float4* hid04 = reinterpret_cast<const float4*>(hid0);
        for (int i = tid; i < BPC * 16; i += THREADS) {
            int b = i >> 4, c = i & 15;
            *reinterpret_cast<float4*>(hGsh + b * HPAD + c * 4) =
                __ldg(&hid04[(cb0 + b) * 16 + c]);
        }
    }
    if (tid < BPC) {
        int gb = cb0 + tid;
        Lsh[tid] = make_float4(__ldg(&last[gb * 3 + 0]),
                               __ldg(&last[gb * 3 + 1]),
                               __ldg(&last[gb * 3 + 2]), 0.0f);
    }

    // ---- Phase A identity: 8-lane group -> one batch, lane -> 8 dims
    const int sub = lane >> 3, lg = lane & 7;
    const int bA  = w * 4 + sub;
    const int gbA = cb0 + bA;
    const float4* Wl4 = reinterpret_cast<const float4*>(Wlin);
    const float4 wl0 = __ldg(&Wl4[lg * 2]);
    const float4 wl1 = __ldg(&Wl4[lg * 2 + 1]);
    const float  bl  = __ldg(blin);

    // encoder slice in registers: 12 t x 8 dims
    const float4* enc4 = reinterpret_cast<const float4*>(enc);
    float4 ev0[T_IN], ev1[T_IN];
#pragma unroll
    for (int t = 0; t < T_IN; t++) {
        int idx = (t * Bz + gbA) * 16 + lg * 2;
        ev0[t] = __ldg(&enc4[idx]);
        ev1[t] = __ldg(&enc4[idx + 1]);
    }

    // ---- Phase B identity: MMA fragment coords
    const int g  = lane >> 2;     // groupID 0..7
    const int t4 = lane & 3;      // threadID-in-group

    __syncthreads();

#pragma unroll 1
    for (int step = 0; step < T_OUT; step++) {
        // ================= Phase A: out(step-1) + attention =================
        float4 h0 = *reinterpret_cast<const float4*>(hGsh + bA * HPAD + lg * 8);
        float4 h1 = *reinterpret_cast<const float4*>(hGsh + bA * HPAD + lg * 8 + 4);

        if (step > 0) {
            float o = dot8(h0, wl0, h1, wl1);
            o += __shfl_xor_sync(FULLMASK, o, 4);
            o += __shfl_xor_sync(FULLMASK, o, 2);
            o += __shfl_xor_sync(FULLMASK, o, 1);
            o += bl;
            if (lg == 0) {
                float4 L = Lsh[bA];
                out[gbA * T_OUT + step - 1] = o;
                Lsh[bA] = make_float4(o, L.x, L.y, 0.0f);
            }
        }

        float p[T_IN];
#pragma unroll
        for (int t = 0; t < T_IN; t++)
            p[t] = dot8(ev0[t], h0, ev1[t], h1);
#pragma unroll
        for (int off = 4; off > 0; off >>= 1)
#pragma unroll
            for (int t = 0; t < T_IN; t++)
                p[t] += __shfl_xor_sync(FULLMASK, p[t], off);

        float m = p[0];
#pragma unroll
        for (int t = 1; t < T_IN; t++) m = fmaxf(m, p[t]);
        float s = 0.0f;
#pragma unroll
        for (int t = 0; t < T_IN; t++) { p[t] = __expf(p[t] - m); s += p[t]; }
        float inv = __fdividef(1.0f, s);

        float4 c0 = make_float4(0.f, 0.f, 0.f, 0.f);
        float4 c1 = make_float4(0.f, 0.f, 0.f, 0.f);
#pragma unroll
        for (int t = 0; t < T_IN; t++) {
            c0.x = fmaf(p[t], ev0[t].x, c0.x); c0.y = fmaf(p[t], ev0[t].y, c0.y);
            c0.z = fmaf(p[t], ev0[t].z, c0.z); c0.w = fmaf(p[t], ev0[t].w, c0.w);
            c1.x = fmaf(p[t], ev1[t].x, c1.x); c1.y = fmaf(p[t], ev1[t].y, c1.y);
            c1.z = fmaf(p[t], ev1[t].z, c1.z); c1.w = fmaf(p[t], ev1[t].w, c1.w);
        }
        h0.x = fmaf(c0.x, inv, h0.x); h0.y = fmaf(c0.y, inv, h0.y);
        h0.z = fmaf(c0.z, inv, h0.z); h0.w = fmaf(c0.w, inv, h0.w);
        h1.x = fmaf(c1.x, inv, h1.x); h1.y = fmaf(c1.y, inv, h1.y);
        h1.z = fmaf(c1.z, inv, h1.z); h1.w = fmaf(c1.w, inv, h1.w);

        *reinterpret_cast<float4*>(hAsh + bA * HPAD + lg * 8)     = h0;
        *reinterpret_cast<float4*>(hAsh + bA * HPAD + lg * 8 + 4) = h1;
        __syncthreads();

        // ============ Phase B: gh = hA @ W_hh^T via tf32 MMA ============
        // warp w computes rows {gate*64 + w*16 + 0..15} for all 16 batches.
        float acc[6][4];
#pragma unroll
        for (int nt = 0; nt < 6; nt++)
#pragma unroll
            for (int ci = 0; ci < 4; ci++) acc[nt][ci] = 0.0f;

#pragma unroll
        for (int kt = 0; kt < 8; kt++) {
            // A fragment: a0:(g, k=kt8+t4) a1:(g+8, same) a2:(g, +4) a3:(g+8, +4)
            unsigned a0 = cvt_tf32(hAsh[g * HPAD + kt * 8 + t4]);
            unsigned a1 = cvt_tf32(hAsh[(g + 8) * HPAD + kt * 8 + t4]);
            unsigned a2 = cvt_tf32(hAsh[g * HPAD + kt * 8 + t4 + 4]);
            unsigned a3 = cvt_tf32(hAsh[(g + 8) * HPAD + kt * 8 + t4 + 4]);
#pragma unroll
            for (int nt = 0; nt < 6; nt++) {
                uint2 bv = Wfr[(((w * 6) + nt) * 8 + kt) * 32 + lane];
                mma_tf32(acc[nt][0], acc[nt][1], acc[nt][2], acc[nt][3],
                         a0, a1, a2, a3, bv.x, bv.y);
            }
        }

        // ---- gates: lane covers batches {g, g+8} x dims {w16+ntp8+2t4, +1}
        float4 Lg0 = Lsh[g];
        float4 Lg8 = Lsh[g + 8];
#pragma unroll
        for (int ntp = 0; ntp < 2; ntp++) {
#pragma unroll
            for (int d01 = 0; d01 < 2; d01++) {
                int dim = w * 16 + ntp * 8 + 2 * t4 + d01;
                float4 gpr = gpsh[dim];
                float4 gpz = gpsh[64 + dim];
                float4 gpn = gpsh[128 + dim];
                float bhr = bhsh[dim], bhz = bhsh[64 + dim], bhn = bhsh[128 + dim];
#pragma unroll
                for (int bb = 0; bb < 2; bb++) {
                    int bat = g + 8 * bb;
                    float4 L = bb ? Lg8 : Lg0;
                    int ci = bb * 2 + d01;
                    float ghr = acc[ntp][ci]     + bhr;
                    float ghz = acc[ntp + 2][ci] + bhz;
                    float ghn = acc[ntp + 4][ci] + bhn;
                    float gir = fmaf(gpr.x, L.x, fmaf(gpr.y, L.y, fmaf(gpr.z, L.z, gpr.w)));
                    float giz = fmaf(gpz.x, L.x, fmaf(gpz.y, L.y, fmaf(gpz.z, L.z, gpz.w)));
                    float gin = fmaf(gpn.x, L.x, fmaf(gpn.y, L.y, fmaf(gpn.z, L.z, gpn.w)));
                    float r = sigf(gir + ghr);
                    float z = sigf(giz + ghz);
                    float n = tanhfast(fmaf(r, ghn, gin));
                    float hprev = hAsh[bat * HPAD + dim];
                    hGsh[bat * HPAD + dim] = fmaf(z, hprev - n, n);
                }
            }
        }
        __syncthreads();
    }

    // ---- final output (step T_OUT-1) from hG ----
    {
        float4 h0 = *reinterpret_cast<const float4*>(hGsh + bA * HPAD + lg * 8);
        float4 h1 = *reinterpret_cast<const float4*>(hGsh + bA * HPAD + lg * 8 + 4);
        float o = dot8(h0, wl0, h1, wl1);
        o += __shfl_xor_sync(FULLMASK, o, 4);
        o += __shfl_xor_sync(FULLMASK, o, 2);
        o += __shfl_xor_sync(FULLMASK, o, 1);
        o += bl;
        if (lg == 0) out[gbA * T_OUT + T_OUT - 1] = o;
    }
}

extern "C" void kernel_launch(void* const* d_in, const int* in_sizes, int n_in,
                              void* d_out, int out_size) {
    const float* enc  = (const float*)d_in[0];
    const float* hid0 = (const float*)d_in[1];
    const float* last = (const float*)d_in[2];
    const float* Wih  = (const float*)d_in[3];
    const float* Whh  = (const float*)d_in[4];
    const float* bih  = (const float*)d_in[5];
    const float* bhh  = (const float*)d_in[6];
    const float* Wlin = (const float*)d_in[7];
    const float* blin = (const float*)d_in[8];
    float* out = (float*)d_out;

    cudaFuncSetAttribute(decoder_kernel,
                         cudaFuncAttributeMaxDynamicSharedMemorySize,
                         SMEM_BYTES);

    dim3 grid(Bz / BPC);   // 4096 CTAs
    decoder_kernel<<<grid, THREADS, SMEM_BYTES>>>(
        enc, hid0, last, Wih, Whh, bih, bhh, Wlin, blin, out);
}